// round 9
// baseline (speedup 1.0000x reference)
#include <cuda_runtime.h>

#define N_NODES  100000
#define N_EDGES  2500000
#define N_GRAPHS 512
#define IN_DIM   14
#define HID      32

#define CONV_TPB    256
#define CONV_BLOCKS 1184    // 9472 warps, grid-stride over nodes

// ---------------- device scratch ----------------
__device__ float4 d_x4[N_NODES * 4];        // x padded 14 -> 16 floats
__device__ float4 d_h0v[N_NODES * 8];
__device__ float4 d_h1v[N_NODES * 8];
__device__ float4 d_pool4[N_GRAPHS * 8];
__device__ int    d_deg[N_NODES];           // degree, then fill cursor
__device__ int    d_off[N_NODES + 1];       // CSR row offsets (by dst)
__device__ int    d_csrc[N_EDGES];          // CSR column = src node of each edge

__device__ __forceinline__ void red_add_v4(float4* p, float4 v) {
    asm volatile("red.global.add.v4.f32 [%0], {%1,%2,%3,%4};"
                 :: "l"(p), "f"(v.x), "f"(v.y), "f"(v.z), "f"(v.w)
                 : "memory");
}

// ---------------- prep: pad x, zero deg + pool ----------------
__global__ void k_prep(const float* __restrict__ x) {
    int i = blockIdx.x * blockDim.x + threadIdx.x;
    if (i < N_NODES) {
        float buf[16];
        #pragma unroll
        for (int k = 0; k < IN_DIM; k++) buf[k] = x[i * IN_DIM + k];
        buf[14] = 0.0f; buf[15] = 0.0f;
        #pragma unroll
        for (int k = 0; k < 4; k++)
            d_x4[i * 4 + k] = make_float4(buf[4*k], buf[4*k+1], buf[4*k+2], buf[4*k+3]);
        d_deg[i] = 0;
    }
    if (i < N_GRAPHS * 8) d_pool4[i] = make_float4(0.f, 0.f, 0.f, 0.f);
}

// ---------------- CSR build ----------------
__global__ void k_hist(const int* __restrict__ ei) {
    int i = blockIdx.x * blockDim.x + threadIdx.x;
    const int4* dst4 = (const int4*)(ei + N_EDGES);
    if (i < N_EDGES / 4) {
        int4 d = dst4[i];
        atomicAdd(&d_deg[d.x], 1);
        atomicAdd(&d_deg[d.y], 1);
        atomicAdd(&d_deg[d.z], 1);
        atomicAdd(&d_deg[d.w], 1);
    }
}

__global__ void k_scan() {
    const int C = (N_NODES + 1023) / 1024;  // 98
    __shared__ int sPart[1024];
    int t = threadIdx.x;
    int start = t * C;
    int sum = 0;
    for (int i = 0; i < C; i++) {
        int idx = start + i;
        if (idx < N_NODES) sum += d_deg[idx];
    }
    sPart[t] = sum;
    __syncthreads();
    for (int off = 1; off < 1024; off <<= 1) {
        int v = (t >= off) ? sPart[t - off] : 0;
        __syncthreads();
        sPart[t] += v;
        __syncthreads();
    }
    int run = (t == 0) ? 0 : sPart[t - 1];
    for (int i = 0; i < C; i++) {
        int idx = start + i;
        if (idx < N_NODES) {
            int d = d_deg[idx];
            d_off[idx] = run;
            d_deg[idx] = run;   // becomes fill cursor
            run += d;
        }
    }
    if (t == 0) d_off[N_NODES] = N_EDGES;
}

__global__ void k_fill(const int* __restrict__ ei) {
    int i = blockIdx.x * blockDim.x + threadIdx.x;
    if (i < N_EDGES) {
        int s = ei[i], d = ei[N_EDGES + i];
        int pos = atomicAdd(&d_deg[d], 1);
        d_csrc[pos] = s;
    }
}

// ---------------- layer 1: pair-packed gather + pipelined prefetch -----------------
__global__ void __launch_bounds__(CONV_TPB) k_conv1(const float* __restrict__ Wrel,
                                                    const float* __restrict__ brel,
                                                    const float* __restrict__ Wroot) {
    __shared__ float2 sWW[IN_DIM * HID];   // (Wrel[k][j], Wroot[k][j])
    __shared__ float sb[HID];
    for (int k = threadIdx.x; k < IN_DIM * HID; k += blockDim.x)
        sWW[k] = make_float2(Wrel[k], Wroot[k]);
    if (threadIdx.x < HID) sb[threadIdx.x] = brel[threadIdx.x];
    __syncthreads();

    const float* xp = (const float*)d_x4;
    float* h0 = (float*)d_h0v;
    int lane = threadIdx.x & 31, w = threadIdx.x >> 5;
    int warpId = blockIdx.x * (CONV_TPB / 32) + w;
    int nWarps = gridDim.x * (CONV_TPB / 32);
    int half = lane >> 4;        // 0/1: neighbor of a pair
    int dim  = lane & 15;

    int n = warpId;
    if (n >= N_NODES) return;
    int beg = d_off[n], end = d_off[n + 1];
    int sidx = (beg + lane < end) ? d_csrc[beg + lane] : 0;

    while (n < N_NODES) {
        int nn = n + nWarps;
        int nbeg = 0, nend = 0;
        if (nn < N_NODES) { nbeg = d_off[nn]; nend = d_off[nn + 1]; }

        float a0 = 0.f, a1 = 0.f, a2 = 0.f, a3 = 0.f;
        int base = beg;
        while (base < end) {
            int rem = end - base; int cnt = rem < 32 ? rem : 32;
            int j = 0;
            for (; j + 8 <= cnt; j += 8) {
                int s0 = __shfl_sync(0xffffffffu, sidx, j + 0 + half);
                int s1 = __shfl_sync(0xffffffffu, sidx, j + 2 + half);
                int s2 = __shfl_sync(0xffffffffu, sidx, j + 4 + half);
                int s3 = __shfl_sync(0xffffffffu, sidx, j + 6 + half);
                a0 += xp[s0 * 16 + dim];
                a1 += xp[s1 * 16 + dim];
                a2 += xp[s2 * 16 + dim];
                a3 += xp[s3 * 16 + dim];
            }
            for (; j + 2 <= cnt; j += 2) {
                int s0 = __shfl_sync(0xffffffffu, sidx, j + half);
                a0 += xp[s0 * 16 + dim];
            }
            if (j < cnt) {
                int s0 = __shfl_sync(0xffffffffu, sidx, j);
                float v = xp[s0 * 16 + dim];
                if (half) v = 0.f;
                a0 += v;
            }
            base += 32;
            if (base < end) sidx = (base + lane < end) ? d_csrc[base + lane] : 0;
        }
        // prefetch next node's first csrc batch (covered by epilogue)
        if (nn < N_NODES) sidx = (nbeg + lane < nend) ? d_csrc[nbeg + lane] : 0;

        float agg = (a0 + a1) + (a2 + a3);
        agg += __shfl_xor_sync(0xffffffffu, agg, 16);   // fold pair halves
        float hs = xp[n * 16 + dim];

        float o = sb[lane];
        #pragma unroll
        for (int k = 0; k < IN_DIM; k++) {
            float2 wk = sWW[k * HID + lane];
            float ak = __shfl_sync(0xffffffffu, agg, k);
            float hk = __shfl_sync(0xffffffffu, hs, k);
            o = fmaf(ak, wk.x, o);
            o = fmaf(hk, wk.y, o);
        }
        h0[n * HID + lane] = fmaxf(o, 0.0f);

        n = nn; beg = nbeg; end = nend;
    }
}

// ---------------- layers 2..5: 8-acc gather + pipelined prefetch -------------------
__global__ void __launch_bounds__(CONV_TPB) k_conv32(int src_is_h0,
                                                     const float* __restrict__ Wrel,
                                                     const float* __restrict__ brel,
                                                     const float* __restrict__ Wroot) {
    __shared__ float2 sWW[HID * HID];      // (Wrel[k][j], Wroot[k][j])
    __shared__ float sb[HID];
    for (int k = threadIdx.x; k < HID * HID; k += blockDim.x)
        sWW[k] = make_float2(Wrel[k], Wroot[k]);
    if (threadIdx.x < HID) sb[threadIdx.x] = brel[threadIdx.x];
    __syncthreads();

    const float* hin = src_is_h0 ? (const float*)d_h0v : (const float*)d_h1v;
    float*      hout = src_is_h0 ? (float*)d_h1v       : (float*)d_h0v;

    int lane = threadIdx.x & 31, w = threadIdx.x >> 5;
    int warpId = blockIdx.x * (CONV_TPB / 32) + w;
    int nWarps = gridDim.x * (CONV_TPB / 32);

    int n = warpId;
    if (n >= N_NODES) return;
    int beg = d_off[n], end = d_off[n + 1];
    int sidx = (beg + lane < end) ? d_csrc[beg + lane] : 0;

    while (n < N_NODES) {
        int nn = n + nWarps;
        int nbeg = 0, nend = 0;
        if (nn < N_NODES) { nbeg = d_off[nn]; nend = d_off[nn + 1]; }

        float a0=0.f,a1=0.f,a2=0.f,a3=0.f,a4=0.f,a5=0.f,a6=0.f,a7=0.f;
        int base = beg;
        while (base < end) {
            int rem = end - base; int cnt = rem < 32 ? rem : 32;
            int j = 0;
            for (; j + 8 <= cnt; j += 8) {
                int s0 = __shfl_sync(0xffffffffu, sidx, j + 0);
                int s1 = __shfl_sync(0xffffffffu, sidx, j + 1);
                int s2 = __shfl_sync(0xffffffffu, sidx, j + 2);
                int s3 = __shfl_sync(0xffffffffu, sidx, j + 3);
                int s4 = __shfl_sync(0xffffffffu, sidx, j + 4);
                int s5 = __shfl_sync(0xffffffffu, sidx, j + 5);
                int s6 = __shfl_sync(0xffffffffu, sidx, j + 6);
                int s7 = __shfl_sync(0xffffffffu, sidx, j + 7);
                a0 += hin[s0 * HID + lane];
                a1 += hin[s1 * HID + lane];
                a2 += hin[s2 * HID + lane];
                a3 += hin[s3 * HID + lane];
                a4 += hin[s4 * HID + lane];
                a5 += hin[s5 * HID + lane];
                a6 += hin[s6 * HID + lane];
                a7 += hin[s7 * HID + lane];
            }
            for (; j + 2 <= cnt; j += 2) {
                int s0 = __shfl_sync(0xffffffffu, sidx, j);
                int s1 = __shfl_sync(0xffffffffu, sidx, j + 1);
                a0 += hin[s0 * HID + lane];
                a1 += hin[s1 * HID + lane];
            }
            if (j < cnt) {
                int s0 = __shfl_sync(0xffffffffu, sidx, j);
                a0 += hin[s0 * HID + lane];
            }
            base += 32;
            if (base < end) sidx = (base + lane < end) ? d_csrc[base + lane] : 0;
        }
        // prefetch next node's first csrc batch (covered by epilogue)
        if (nn < N_NODES) sidx = (nbeg + lane < nend) ? d_csrc[nbeg + lane] : 0;

        float agg = ((a0 + a1) + (a2 + a3)) + ((a4 + a5) + (a6 + a7));
        float hs  = hin[n * HID + lane];

        float o = sb[lane];
        #pragma unroll
        for (int k = 0; k < HID; k++) {
            float2 wk = sWW[k * HID + lane];
            float ak = __shfl_sync(0xffffffffu, agg, k);
            float hk = __shfl_sync(0xffffffffu, hs, k);
            o = fmaf(ak, wk.x, o);
            o = fmaf(hk, wk.y, o);
        }
        hout[n * HID + lane] = fmaxf(o, 0.0f);

        n = nn; beg = nbeg; end = nend;
    }
}

// ---------------- sum-pool per graph ----------------
__global__ void k_pool(int src_is_h0, const int* __restrict__ batch) {
    int t = blockIdx.x * blockDim.x + threadIdx.x;
    if (t >= 8 * N_NODES) return;
    const float4* h = src_is_h0 ? d_h0v : d_h1v;
    int n = t >> 3, c = t & 7;
    int g = batch[n];
    float4 v = h[n * 8 + c];
    red_add_v4(&d_pool4[g * 8 + c], v);
}

// ---------------- MLP head + log_softmax ----------------
__global__ void k_head(const float* __restrict__ lin1w, const float* __restrict__ lin1b,
                       const float* __restrict__ lin2w, const float* __restrict__ lin2b,
                       float* __restrict__ out) {
    __shared__ float s1[HID * HID], sb1[HID], s2[HID * 2], sb2[2];
    for (int k = threadIdx.x; k < HID * HID; k += blockDim.x) s1[k] = lin1w[k];
    if (threadIdx.x < HID)     sb1[threadIdx.x] = lin1b[threadIdx.x];
    if (threadIdx.x < HID * 2) s2[threadIdx.x]  = lin2w[threadIdx.x];
    if (threadIdx.x < 2)       sb2[threadIdx.x] = lin2b[threadIdx.x];
    __syncthreads();

    int g = threadIdx.x;
    if (g >= N_GRAPHS) return;

    const float* pool = (const float*)d_pool4;
    float gr[HID];
    #pragma unroll
    for (int k = 0; k < HID; k++) gr[k] = pool[g * HID + k];

    float hid[HID];
    for (int j = 0; j < HID; j++) {
        float acc = sb1[j];
        #pragma unroll
        for (int k = 0; k < HID; k++) acc += gr[k] * s1[k * HID + j];
        hid[j] = fmaxf(acc, 0.0f);
    }
    float l0 = sb2[0], l1 = sb2[1];
    #pragma unroll
    for (int k = 0; k < HID; k++) {
        l0 += hid[k] * s2[k * 2 + 0];
        l1 += hid[k] * s2[k * 2 + 1];
    }
    float m   = fmaxf(l0, l1);
    float lse = m + logf(expf(l0 - m) + expf(l1 - m));
    out[g * 2 + 0] = l0 - lse;
    out[g * 2 + 1] = l1 - lse;
}

// ---------------- launch: inputs identified BY ELEMENT COUNT (order-agnostic) -------
extern "C" void kernel_launch(void* const* d_in, const int* in_sizes, int n_in,
                              void* d_out, int out_size) {
    const float *x = 0, *Wrel1 = 0, *brel1 = 0, *Wroot1 = 0;
    const float *Wrel = 0, *brel = 0, *Wroot = 0;
    const float *lin1w = 0, *lin1b = 0, *lin2w = 0, *lin2b = 0;
    const int *ei = 0, *batch = 0;

    for (int i = 0; i < n_in; i++) {
        int sz = in_sizes[i];
        const void* p = d_in[i];
        switch (sz) {
            case 1400000: x      = (const float*)p; break;
            case 5000000: ei     = (const int*)p; break;
            case 100000:  batch  = (const int*)p; break;
            case 448:     if (!Wrel1) Wrel1 = (const float*)p; else Wroot1 = (const float*)p; break;
            case 4096:    if (!Wrel)  Wrel  = (const float*)p; else Wroot  = (const float*)p; break;
            case 32:      if (!brel1) brel1 = (const float*)p; else lin1b  = (const float*)p; break;
            case 128:     brel   = (const float*)p; break;
            case 1024:    lin1w  = (const float*)p; break;
            case 64:      lin2w  = (const float*)p; break;
            case 2:       lin2b  = (const float*)p; break;
            default: break;
        }
    }
    float* out = (float*)d_out;

    const int TB = 256;

    // prep + CSR build
    k_prep<<<(N_NODES + TB - 1) / TB, TB>>>(x);
    k_hist<<<(N_EDGES / 4 + TB - 1) / TB, TB>>>(ei);
    k_scan<<<1, 1024>>>();
    k_fill<<<(N_EDGES + TB - 1) / TB, TB>>>(ei);

    // layer 1 -> h0
    k_conv1<<<CONV_BLOCKS, CONV_TPB>>>(Wrel1, brel1, Wroot1);

    // layers 2..5 : ping-pong h0 <-> h1
    int src_is_h0 = 1;
    for (int i = 0; i < 4; i++) {
        k_conv32<<<CONV_BLOCKS, CONV_TPB>>>(
            src_is_h0,
            Wrel  + i * HID * HID,
            brel  + i * HID,
            Wroot + i * HID * HID);
        src_is_h0 ^= 1;
    }

    // final h lives in h0
    k_pool<<<(8 * N_NODES + TB - 1) / TB, TB>>>(src_is_h0, batch);
    k_head<<<1, N_GRAPHS>>>(lin1w, lin1b, lin2w, lin2b, out);
}

// round 10
// speedup vs baseline: 1.2043x; 1.2043x over previous
#include <cuda_runtime.h>

#define N_NODES  100000
#define N_EDGES  2500000
#define N_GRAPHS 512
#define IN_DIM   14
#define HID      32

#define CONV_TPB    512
#define CONV_BLOCKS 592     // 9472 warps, grid-stride over nodes (R6-proven config)

// ---------------- device scratch ----------------
__device__ float4 d_x4[N_NODES * 4];        // x padded 14 -> 16 floats
__device__ float4 d_h0v[N_NODES * 8];
__device__ float4 d_h1v[N_NODES * 8];
__device__ float4 d_pool4[N_GRAPHS * 8];
__device__ int    d_deg[N_NODES];           // degree, then fill cursor
__device__ int    d_off[N_NODES + 1];       // CSR row offsets (by dst)
__device__ int    d_csrc[N_EDGES];          // CSR column = src node of each edge

__device__ __forceinline__ void red_add_v4(float4* p, float4 v) {
    asm volatile("red.global.add.v4.f32 [%0], {%1,%2,%3,%4};"
                 :: "l"(p), "f"(v.x), "f"(v.y), "f"(v.z), "f"(v.w)
                 : "memory");
}

// ---------------- prep: pad x, zero deg + pool ----------------
__global__ void k_prep(const float* __restrict__ x) {
    int i = blockIdx.x * blockDim.x + threadIdx.x;
    if (i < N_NODES) {
        float buf[16];
        #pragma unroll
        for (int k = 0; k < IN_DIM; k++) buf[k] = x[i * IN_DIM + k];
        buf[14] = 0.0f; buf[15] = 0.0f;
        #pragma unroll
        for (int k = 0; k < 4; k++)
            d_x4[i * 4 + k] = make_float4(buf[4*k], buf[4*k+1], buf[4*k+2], buf[4*k+3]);
        d_deg[i] = 0;
    }
    if (i < N_GRAPHS * 8) d_pool4[i] = make_float4(0.f, 0.f, 0.f, 0.f);
}

// ---------------- CSR build ----------------
__global__ void k_hist(const int* __restrict__ ei) {
    int i = blockIdx.x * blockDim.x + threadIdx.x;
    const int4* dst4 = (const int4*)(ei + N_EDGES);
    if (i < N_EDGES / 4) {
        int4 d = dst4[i];
        atomicAdd(&d_deg[d.x], 1);
        atomicAdd(&d_deg[d.y], 1);
        atomicAdd(&d_deg[d.z], 1);
        atomicAdd(&d_deg[d.w], 1);
    }
}

__global__ void k_scan() {
    const int C = (N_NODES + 1023) / 1024;  // 98
    __shared__ int sPart[1024];
    int t = threadIdx.x;
    int start = t * C;
    int sum = 0;
    for (int i = 0; i < C; i++) {
        int idx = start + i;
        if (idx < N_NODES) sum += d_deg[idx];
    }
    sPart[t] = sum;
    __syncthreads();
    for (int off = 1; off < 1024; off <<= 1) {
        int v = (t >= off) ? sPart[t - off] : 0;
        __syncthreads();
        sPart[t] += v;
        __syncthreads();
    }
    int run = (t == 0) ? 0 : sPart[t - 1];
    for (int i = 0; i < C; i++) {
        int idx = start + i;
        if (idx < N_NODES) {
            int d = d_deg[idx];
            d_off[idx] = run;
            d_deg[idx] = run;   // becomes fill cursor
            run += d;
        }
    }
    if (t == 0) d_off[N_NODES] = N_EDGES;
}

__global__ void k_fill(const int* __restrict__ ei) {
    int i = blockIdx.x * blockDim.x + threadIdx.x;
    if (i < N_EDGES) {
        int s = ei[i], d = ei[N_EDGES + i];
        int pos = atomicAdd(&d_deg[d], 1);
        d_csrc[pos] = s;
    }
}

// ---------------- layer 1: 8-edges/LDG.128 gather + smem epilogue ------------------
// 4 lanes per edge: grp = lane>>2 (edge within batch), sub = lane&3 (float4 index)
__global__ void __launch_bounds__(CONV_TPB) k_conv1(const float* __restrict__ Wrel,
                                                    const float* __restrict__ brel,
                                                    const float* __restrict__ Wroot) {
    __shared__ float sW[IN_DIM * HID], sWr[IN_DIM * HID], sb[HID];
    __shared__ __align__(16) float sAgg[16][16];
    __shared__ float sHin[16][16];
    for (int k = threadIdx.x; k < IN_DIM * HID; k += blockDim.x) {
        sW[k]  = Wrel[k];
        sWr[k] = Wroot[k];
    }
    if (threadIdx.x < HID) sb[threadIdx.x] = brel[threadIdx.x];
    __syncthreads();

    const float4* xp4 = d_x4;
    const float*  xp  = (const float*)d_x4;
    float* h0 = (float*)d_h0v;
    int lane = threadIdx.x & 31, w = threadIdx.x >> 5;
    int warpId = blockIdx.x * (CONV_TPB / 32) + w;
    int nWarps = gridDim.x * (CONV_TPB / 32);
    int grp = lane >> 2;     // 0..7: edge within 8-edge batch
    int sub = lane & 3;      // 0..3: float4 within 16-float row

    for (int n = warpId; n < N_NODES; n += nWarps) {
        int beg = d_off[n], end = d_off[n + 1];
        float4 acc0 = make_float4(0.f,0.f,0.f,0.f);
        float4 acc1 = make_float4(0.f,0.f,0.f,0.f);
        for (int base = beg; base < end; base += 32) {
            int cnt = end - base; if (cnt > 32) cnt = 32;
            int sidx = (base + lane < end) ? d_csrc[base + lane] : 0;
            int j = 0;
            for (; j + 16 <= cnt; j += 16) {
                int sa = __shfl_sync(0xffffffffu, sidx, j + grp);
                int sb_ = __shfl_sync(0xffffffffu, sidx, j + 8 + grp);
                float4 va = xp4[sa * 4 + sub];
                float4 vb = xp4[sb_ * 4 + sub];
                acc0.x += va.x; acc0.y += va.y; acc0.z += va.z; acc0.w += va.w;
                acc1.x += vb.x; acc1.y += vb.y; acc1.z += vb.z; acc1.w += vb.w;
            }
            for (; j < cnt; j += 8) {
                int s = __shfl_sync(0xffffffffu, sidx, j + grp);
                if (j + grp < cnt) {
                    float4 v = xp4[s * 4 + sub];
                    acc0.x += v.x; acc0.y += v.y; acc0.z += v.z; acc0.w += v.w;
                }
            }
        }
        float4 acc = make_float4(acc0.x + acc1.x, acc0.y + acc1.y,
                                 acc0.z + acc1.z, acc0.w + acc1.w);
        // reduce across 8 edge-groups (lane bits 2..4): xor 4, 8, 16
        #pragma unroll
        for (int d = 4; d <= 16; d <<= 1) {
            acc.x += __shfl_xor_sync(0xffffffffu, acc.x, d);
            acc.y += __shfl_xor_sync(0xffffffffu, acc.y, d);
            acc.z += __shfl_xor_sync(0xffffffffu, acc.z, d);
            acc.w += __shfl_xor_sync(0xffffffffu, acc.w, d);
        }
        if (lane < 4) ((float4*)sAgg[w])[lane] = acc;   // lanes 0..3: sub=0..3
        if (lane < 16) sHin[w][lane] = xp[n * 16 + lane];
        __syncwarp();

        float o = sb[lane];
        #pragma unroll
        for (int k = 0; k < IN_DIM; k++)
            o += sAgg[w][k] * sW[k * HID + lane] + sHin[w][k] * sWr[k * HID + lane];
        h0[n * HID + lane] = fmaxf(o, 0.0f);
        __syncwarp();
    }
}

// ---------------- layers 2..5: 4-edges/LDG.128 gather + smem epilogue --------------
// 8 lanes per edge: grp = lane>>3 (edge within batch), sub = lane&7 (float4 index)
__global__ void __launch_bounds__(CONV_TPB) k_conv32(int src_is_h0,
                                                     const float* __restrict__ Wrel,
                                                     const float* __restrict__ brel,
                                                     const float* __restrict__ Wroot) {
    __shared__ float sW[HID * HID], sWr[HID * HID], sb[HID];
    __shared__ __align__(16) float sAgg[16][HID];
    __shared__ float sHin[16][HID];
    for (int k = threadIdx.x; k < HID * HID; k += blockDim.x) {
        sW[k]  = Wrel[k];
        sWr[k] = Wroot[k];
    }
    if (threadIdx.x < HID) sb[threadIdx.x] = brel[threadIdx.x];
    __syncthreads();

    const float4* hin4 = src_is_h0 ? d_h0v : d_h1v;
    const float*  hin  = (const float*)hin4;
    float*        hout = src_is_h0 ? (float*)d_h1v : (float*)d_h0v;

    int lane = threadIdx.x & 31, w = threadIdx.x >> 5;
    int warpId = blockIdx.x * (CONV_TPB / 32) + w;
    int nWarps = gridDim.x * (CONV_TPB / 32);
    int grp = lane >> 3;     // 0..3: edge within 4-edge batch
    int sub = lane & 7;      // 0..7: float4 within 32-float row

    for (int n = warpId; n < N_NODES; n += nWarps) {
        int beg = d_off[n], end = d_off[n + 1];
        float4 acc0 = make_float4(0.f,0.f,0.f,0.f);
        float4 acc1 = make_float4(0.f,0.f,0.f,0.f);
        for (int base = beg; base < end; base += 32) {
            int cnt = end - base; if (cnt > 32) cnt = 32;
            int sidx = (base + lane < end) ? d_csrc[base + lane] : 0;
            int j = 0;
            for (; j + 8 <= cnt; j += 8) {
                int sa = __shfl_sync(0xffffffffu, sidx, j + grp);
                int sb_ = __shfl_sync(0xffffffffu, sidx, j + 4 + grp);
                float4 va = hin4[sa * 8 + sub];
                float4 vb = hin4[sb_ * 8 + sub];
                acc0.x += va.x; acc0.y += va.y; acc0.z += va.z; acc0.w += va.w;
                acc1.x += vb.x; acc1.y += vb.y; acc1.z += vb.z; acc1.w += vb.w;
            }
            for (; j < cnt; j += 4) {
                int s = __shfl_sync(0xffffffffu, sidx, j + grp);
                if (j + grp < cnt) {
                    float4 v = hin4[s * 8 + sub];
                    acc0.x += v.x; acc0.y += v.y; acc0.z += v.z; acc0.w += v.w;
                }
            }
        }
        float4 acc = make_float4(acc0.x + acc1.x, acc0.y + acc1.y,
                                 acc0.z + acc1.z, acc0.w + acc1.w);
        // reduce across 4 edge-groups (lane bits 3..4): xor 8, 16
        #pragma unroll
        for (int d = 8; d <= 16; d <<= 1) {
            acc.x += __shfl_xor_sync(0xffffffffu, acc.x, d);
            acc.y += __shfl_xor_sync(0xffffffffu, acc.y, d);
            acc.z += __shfl_xor_sync(0xffffffffu, acc.z, d);
            acc.w += __shfl_xor_sync(0xffffffffu, acc.w, d);
        }
        if (lane < 8) ((float4*)sAgg[w])[lane] = acc;   // lanes 0..7: sub=0..7
        sHin[w][lane] = hin[n * HID + lane];
        __syncwarp();

        float o = sb[lane];
        #pragma unroll
        for (int k = 0; k < HID; k++)
            o += sAgg[w][k] * sW[k * HID + lane] + sHin[w][k] * sWr[k * HID + lane];
        hout[n * HID + lane] = fmaxf(o, 0.0f);
        __syncwarp();
    }
}

// ---------------- sum-pool per graph ----------------
__global__ void k_pool(int src_is_h0, const int* __restrict__ batch) {
    int t = blockIdx.x * blockDim.x + threadIdx.x;
    if (t >= 8 * N_NODES) return;
    const float4* h = src_is_h0 ? d_h0v : d_h1v;
    int n = t >> 3, c = t & 7;
    int g = batch[n];
    float4 v = h[n * 8 + c];
    red_add_v4(&d_pool4[g * 8 + c], v);
}

// ---------------- MLP head + log_softmax ----------------
__global__ void k_head(const float* __restrict__ lin1w, const float* __restrict__ lin1b,
                       const float* __restrict__ lin2w, const float* __restrict__ lin2b,
                       float* __restrict__ out) {
    __shared__ float s1[HID * HID], sb1[HID], s2[HID * 2], sb2[2];
    for (int k = threadIdx.x; k < HID * HID; k += blockDim.x) s1[k] = lin1w[k];
    if (threadIdx.x < HID)     sb1[threadIdx.x] = lin1b[threadIdx.x];
    if (threadIdx.x < HID * 2) s2[threadIdx.x]  = lin2w[threadIdx.x];
    if (threadIdx.x < 2)       sb2[threadIdx.x] = lin2b[threadIdx.x];
    __syncthreads();

    int g = threadIdx.x;
    if (g >= N_GRAPHS) return;

    const float* pool = (const float*)d_pool4;
    float gr[HID];
    #pragma unroll
    for (int k = 0; k < HID; k++) gr[k] = pool[g * HID + k];

    float hid[HID];
    for (int j = 0; j < HID; j++) {
        float acc = sb1[j];
        #pragma unroll
        for (int k = 0; k < HID; k++) acc += gr[k] * s1[k * HID + j];
        hid[j] = fmaxf(acc, 0.0f);
    }
    float l0 = sb2[0], l1 = sb2[1];
    #pragma unroll
    for (int k = 0; k < HID; k++) {
        l0 += hid[k] * s2[k * 2 + 0];
        l1 += hid[k] * s2[k * 2 + 1];
    }
    float m   = fmaxf(l0, l1);
    float lse = m + logf(expf(l0 - m) + expf(l1 - m));
    out[g * 2 + 0] = l0 - lse;
    out[g * 2 + 1] = l1 - lse;
}

// ---------------- launch: inputs identified BY ELEMENT COUNT (order-agnostic) -------
extern "C" void kernel_launch(void* const* d_in, const int* in_sizes, int n_in,
                              void* d_out, int out_size) {
    const float *x = 0, *Wrel1 = 0, *brel1 = 0, *Wroot1 = 0;
    const float *Wrel = 0, *brel = 0, *Wroot = 0;
    const float *lin1w = 0, *lin1b = 0, *lin2w = 0, *lin2b = 0;
    const int *ei = 0, *batch = 0;

    for (int i = 0; i < n_in; i++) {
        int sz = in_sizes[i];
        const void* p = d_in[i];
        switch (sz) {
            case 1400000: x      = (const float*)p; break;
            case 5000000: ei     = (const int*)p; break;
            case 100000:  batch  = (const int*)p; break;
            case 448:     if (!Wrel1) Wrel1 = (const float*)p; else Wroot1 = (const float*)p; break;
            case 4096:    if (!Wrel)  Wrel  = (const float*)p; else Wroot  = (const float*)p; break;
            case 32:      if (!brel1) brel1 = (const float*)p; else lin1b  = (const float*)p; break;
            case 128:     brel   = (const float*)p; break;
            case 1024:    lin1w  = (const float*)p; break;
            case 64:      lin2w  = (const float*)p; break;
            case 2:       lin2b  = (const float*)p; break;
            default: break;
        }
    }
    float* out = (float*)d_out;

    const int TB = 256;

    // prep + CSR build
    k_prep<<<(N_NODES + TB - 1) / TB, TB>>>(x);
    k_hist<<<(N_EDGES / 4 + TB - 1) / TB, TB>>>(ei);
    k_scan<<<1, 1024>>>();
    k_fill<<<(N_EDGES + TB - 1) / TB, TB>>>(ei);

    // layer 1 -> h0
    k_conv1<<<CONV_BLOCKS, CONV_TPB>>>(Wrel1, brel1, Wroot1);

    // layers 2..5 : ping-pong h0 <-> h1
    int src_is_h0 = 1;
    for (int i = 0; i < 4; i++) {
        k_conv32<<<CONV_BLOCKS, CONV_TPB>>>(
            src_is_h0,
            Wrel  + i * HID * HID,
            brel  + i * HID,
            Wroot + i * HID * HID);
        src_is_h0 ^= 1;
    }

    // final h lives in h0
    k_pool<<<(8 * N_NODES + TB - 1) / TB, TB>>>(src_is_h0, batch);
    k_head<<<1, N_GRAPHS>>>(lin1w, lin1b, lin2w, lin2b, out);
}